// round 1
// baseline (speedup 1.0000x reference)
#include <cuda_runtime.h>

#define NQ 9
#define HOUT 128
#define WOUT 128
#define HW 384

__device__ float d_A[NQ];
__device__ float d_B[NQ];

// Tiny setup: collapse the per-qubit unitary U = Rx(a2)Rz(a1)Rx(a0) acting on
// Ry(theta)|0> into  <Z> = A*sin(theta) + B*cos(theta).
__global__ void quan_setup_kernel(const float* __restrict__ w) {
    int q = threadIdx.x;
    if (q < NQ) {
        const float M = 0.63245553203367586640f;  // sqrt(2/5) = W_MUL
        float a0 = w[3 * q + 0] * M;
        float a1 = w[3 * q + 1] * M;
        float a2 = w[3 * q + 2] * M;
        float s0, c0, s1, c1, s2, c2;
        sincosf(a0, &s0, &c0);
        sincosf(a1, &s1, &c1);
        sincosf(a2, &s2, &c2);
        d_A[q] = s1 * s2;
        d_B[q] = c0 * c2 - s0 * c1 * s2;
    }
}

__global__ void __launch_bounds__(256) quanconv_kernel(
    const float* __restrict__ in, float* __restrict__ out) {
    __shared__ float sA[NQ], sB[NQ];
    int t = threadIdx.x;
    if (t < NQ) { sA[t] = d_A[t]; sB[t] = d_B[t]; }
    __syncthreads();

    int gid = blockIdx.x * 256 + t;     // 0 .. 65535  (= 4*128*128 windows)
    int wo = gid & (WOUT - 1);
    int ho = (gid >> 7) & (HOUT - 1);
    int b  = gid >> 14;

    const float* base = in + ((size_t)(b * HW) + ho * 3) * HW + wo * 3;

    float z[NQ];
#pragma unroll
    for (int kr = 0; kr < 3; kr++) {
        const float* row = base + kr * HW;
#pragma unroll
        for (int kc = 0; kc < 3; kc++) {
            float x = row[kc];
            float sp, cp;
            sincospif(x, &sp, &cp);     // sin(pi*x), cos(pi*x)
            int q = kr * 3 + kc;
            z[q] = fmaf(sA[q], sp, sB[q] * cp);
        }
    }

    // out[0] = prod_{q=1..8} z_q ; out[j>=1] = prod_{q=0..j} z_q
    float s = z[8];
#pragma unroll
    for (int q = 7; q >= 1; q--) s *= z[q];

    float* obase = out + (size_t)b * NQ * HOUT * WOUT + (size_t)ho * WOUT + wo;
    obase[0] = s;
    float p = z[0];
#pragma unroll
    for (int j = 1; j < NQ; j++) {
        p *= z[j];
        obase[(size_t)j * HOUT * WOUT] = p;
    }
}

extern "C" void kernel_launch(void* const* d_in, const int* in_sizes, int n_in,
                              void* d_out, int out_size) {
    const float* x = (const float*)d_in[0];   // (4,1,384,384) float32
    const float* w = (const float*)d_in[1];   // (27,) float32
    float* out = (float*)d_out;               // (4,9,128,128) float32

    quan_setup_kernel<<<1, 32>>>(w);
    quanconv_kernel<<<65536 / 256, 256>>>(x, out);
}

// round 3
// speedup vs baseline: 1.2605x; 1.2605x over previous
#include <cuda_runtime.h>

#define NQ 9
#define HOUT 128
#define WOUT 128
#define HW 384

// One fused kernel:
//  - threads 0..8 collapse U = Rx(a2)Rz(a1)Rx(a0) on Ry(pi*x)|0> into
//      <Z> = A*sin(pi x) + B*cos(pi x) = R * sin(pi x + phi)
//  - block = one output row (b, ho): stage 3 contiguous input rows to smem
//    (float4, fully coalesced), each thread computes one 3x3 window.
__global__ void __launch_bounds__(128) quanconv_fused(
    const float* __restrict__ in, const float* __restrict__ w,
    float* __restrict__ out) {

    __shared__ float sR[NQ];
    __shared__ float sPhi[NQ];
    __shared__ float4 srow4[3 * HW / 4];      // 16B-aligned staging buffer
    float* srow = (float*)srow4;

    const int tid = threadIdx.x;             // wo = tid, 0..127
    const int blk = blockIdx.x;              // 0..511
    const int ho  = blk & (HOUT - 1);
    const int b   = blk >> 7;

    if (tid < NQ) {
        const float M = 0.63245553203367586640f;   // sqrt(2/5) = W_MUL
        float a0 = w[3 * tid + 0] * M;
        float a1 = w[3 * tid + 1] * M;
        float a2 = w[3 * tid + 2] * M;
        float s0, c0, s1, c1, s2, c2;
        sincosf(a0, &s0, &c0);
        sincosf(a1, &s1, &c1);
        sincosf(a2, &s2, &c2);
        float A = s1 * s2;
        float B = c0 * c2 - s0 * c1 * s2;
        sR[tid]   = sqrtf(A * A + B * B);
        sPhi[tid] = atan2f(B, A);
    }

    // rows 3ho..3ho+2 are contiguous in memory: copy 3*384 floats = 288 float4
    const float4* g4 = (const float4*)(in + ((size_t)b * HW + ho * 3) * HW);
    for (int i = tid; i < 3 * (HW / 4); i += 128) srow4[i] = g4[i];

    __syncthreads();

    const float PI_F = 3.14159274101257324219f;
    float z[NQ];
#pragma unroll
    for (int kr = 0; kr < 3; kr++) {
#pragma unroll
        for (int kc = 0; kc < 3; kc++) {
            int q = kr * 3 + kc;
            float x = srow[kr * HW + 3 * tid + kc];
            float t = fmaf(PI_F, x, sPhi[q]);
            z[q] = sR[q] * __sinf(t);
        }
    }

    // out[0] = prod_{q=1..8} z_q ; out[j>=1] = prod_{q=0..j} z_q
    float s = z[8];
#pragma unroll
    for (int q = 7; q >= 1; q--) s *= z[q];

    float* obase = out + (size_t)b * NQ * HOUT * WOUT + (size_t)ho * WOUT + tid;
    obase[0] = s;
    float p = z[0];
#pragma unroll
    for (int j = 1; j < NQ; j++) {
        p *= z[j];
        obase[(size_t)j * HOUT * WOUT] = p;
    }
}

extern "C" void kernel_launch(void* const* d_in, const int* in_sizes, int n_in,
                              void* d_out, int out_size) {
    const float* x = (const float*)d_in[0];   // (4,1,384,384) float32
    const float* w = (const float*)d_in[1];   // (27,) float32
    float* out = (float*)d_out;               // (4,9,128,128) float32

    quanconv_fused<<<4 * HOUT, 128>>>(x, w, out);
}

// round 4
// speedup vs baseline: 1.3092x; 1.0386x over previous
#include <cuda_runtime.h>

#define NQ 9
#define HOUT 128
#define WOUT 128
#define HW 384

// Single fused kernel, one thread per 3x3 window.
//  - 9 window loads issued FIRST (independent of the setup barrier) so DRAM
//    latency overlaps the per-block setup.
//  - setup parallelized: 27 lanes do one sincosf each, 9 lanes combine into
//    A,B per qubit (no atan2/sqrt). Chain ~= one sincosf.
//  - per pixel: z = A*sin(pi x) + B*cos(pi x) via __sincosf (2 MUFU).
__global__ void __launch_bounds__(256) quanconv_fused(
    const float* __restrict__ in, const float* __restrict__ w,
    float* __restrict__ out) {

    __shared__ float sS[27], sC[27];
    __shared__ float sA[NQ], sB[NQ];

    const int tid = threadIdx.x;
    const int gid = blockIdx.x * 256 + tid;     // 0..65535 windows
    const int wo = gid & (WOUT - 1);
    const int ho = (gid >> 7) & (HOUT - 1);
    const int b  = gid >> 14;

    // ---- issue window loads early (before any barrier) ----
    const float* base = in + ((size_t)b * HW + ho * 3) * HW + wo * 3;
    float x[NQ];
#pragma unroll
    for (int kr = 0; kr < 3; kr++)
#pragma unroll
        for (int kc = 0; kc < 3; kc++)
            x[kr * 3 + kc] = __ldg(base + kr * HW + kc);

    // ---- cheap parallel setup in warp 0 ----
    if (tid < 32) {
        if (tid < 27) {
            const float M = 0.63245553203367586640f;  // sqrt(2/5) = W_MUL
            float s, c;
            sincosf(w[tid] * M, &s, &c);
            sS[tid] = s;
            sC[tid] = c;
        }
        __syncwarp();
        if (tid < NQ) {
            float s0 = sS[3 * tid], c0 = sC[3 * tid];
            float s1 = sS[3 * tid + 1], c1 = sC[3 * tid + 1];
            float s2 = sS[3 * tid + 2], c2 = sC[3 * tid + 2];
            sA[tid] = s1 * s2;
            sB[tid] = c0 * c2 - s0 * c1 * s2;
        }
    }
    __syncthreads();

    const float PI_F = 3.14159274101257324219f;
    float z[NQ];
#pragma unroll
    for (int q = 0; q < NQ; q++) {
        float s, c;
        __sincosf(PI_F * x[q], &s, &c);
        z[q] = fmaf(sA[q], s, sB[q] * c);
    }

    // out[0] = prod_{q=1..8} z_q ; out[j>=1] = prod_{q=0..j} z_q
    float suf = z[8];
#pragma unroll
    for (int q = 7; q >= 1; q--) suf *= z[q];

    float* obase = out + (size_t)b * NQ * HOUT * WOUT + (size_t)ho * WOUT + wo;
    obase[0] = suf;
    float p = z[0];
#pragma unroll
    for (int j = 1; j < NQ; j++) {
        p *= z[j];
        obase[(size_t)j * HOUT * WOUT] = p;
    }
}

extern "C" void kernel_launch(void* const* d_in, const int* in_sizes, int n_in,
                              void* d_out, int out_size) {
    const float* x = (const float*)d_in[0];   // (4,1,384,384) float32
    const float* w = (const float*)d_in[1];   // (27,) float32
    float* out = (float*)d_out;               // (4,9,128,128) float32

    quanconv_fused<<<65536 / 256, 256>>>(x, w, out);
}